// round 2
// baseline (speedup 1.0000x reference)
#include <cuda_runtime.h>
#include <math.h>

// Problem constants (fixed shapes per reference setup_inputs)
constexpr int NN = 100000;   // nodes
constexpr int FF = 512;      // input features
constexpr int HH = 256;      // hidden
constexpr int CC = 64;       // classes
constexpr int EE = 3200000;  // edges
constexpr float F_ALPHA = 0.1f;
constexpr int K_HOPS = 10;

// ---------------- static device scratch (no allocs allowed) ----------------
__device__ int      g_degcnt[NN];
__device__ float    g_dinv[NN];
__device__ int      g_rowptr[NN + 1];
__device__ int      g_cursor[NN];
__device__ int      g_esrc[EE];
__device__ float    g_eval[EE];
__device__ float    g_h1[(size_t)NN * HH];
__device__ float    g_h[(size_t)NN * CC];
__device__ float    g_zA[(size_t)NN * CC];
__device__ float    g_zB[(size_t)NN * CC];
__device__ unsigned g_colmax_enc[CC];
__device__ float    g_colmax[CC];
__device__ float    g_colsum[CC];
__device__ int      g_chunksums[512];

static inline int cdiv(int a, int b) { return (a + b - 1) / b; }

// ---------------- graph preprocessing ----------------

__global__ void k_zero_deg(int N) {
    int i = blockIdx.x * blockDim.x + threadIdx.x;
    if (i < N) g_degcnt[i] = 0;
}

// count in-degree (by dst). edge_index is int32 [2, E] (JAX x64 disabled).
__global__ void k_count(const int* __restrict__ ei, int E) {
    int e = blockIdx.x * blockDim.x + threadIdx.x;
    if (e < E) {
        int d = ei[E + e];
        atomicAdd(&g_degcnt[d], 1);
    }
}

__global__ void k_dinv(int N) {
    int i = blockIdx.x * blockDim.x + threadIdx.x;
    if (i < N) g_dinv[i] = rsqrtf((float)g_degcnt[i] + 1.0f);  // +1 self loop
}

// 3-kernel exclusive scan over degcnt -> rowptr (chunk = 512)
__global__ void k_chunksum(int N) {
    __shared__ int s[512];
    int i = blockIdx.x * 512 + threadIdx.x;
    s[threadIdx.x] = (i < N) ? g_degcnt[i] : 0;
    __syncthreads();
    for (int off = 256; off > 0; off >>= 1) {
        if (threadIdx.x < off) s[threadIdx.x] += s[threadIdx.x + off];
        __syncthreads();
    }
    if (threadIdx.x == 0) g_chunksums[blockIdx.x] = s[0];
}

__global__ void k_scanchunks(int NB) {
    int acc = 0;
    for (int b = 0; b < NB; b++) {
        int t = g_chunksums[b];
        g_chunksums[b] = acc;
        acc += t;
    }
}

__global__ void k_scan2(int N) {
    __shared__ int s[512];
    int i = blockIdx.x * 512 + threadIdx.x;
    int c = (i < N) ? g_degcnt[i] : 0;
    s[threadIdx.x] = c;
    __syncthreads();
    for (int off = 1; off < 512; off <<= 1) {
        int v = s[threadIdx.x];
        if (threadIdx.x >= off) v += s[threadIdx.x - off];
        __syncthreads();
        s[threadIdx.x] = v;
        __syncthreads();
    }
    int excl = s[threadIdx.x] - c + g_chunksums[blockIdx.x];
    if (i < N) {
        g_rowptr[i] = excl;
        g_cursor[i] = excl;
        if (i == N - 1) g_rowptr[N] = excl + c;
    }
}

// scatter edges into CSR (by dst), value = (1-alpha)*dinv[src]*dinv[dst]
__global__ void k_scatter(const int* __restrict__ ei, int E) {
    int e = blockIdx.x * blockDim.x + threadIdx.x;
    if (e < E) {
        int s = ei[e];
        int d = ei[E + e];
        int pos = atomicAdd(&g_cursor[d], 1);
        g_esrc[pos] = s;
        g_eval[pos] = (1.0f - F_ALPHA) * g_dinv[s] * g_dinv[d];
    }
}

// ---------------- SGEMM (register-tiled, fp32) ----------------
// mode 0: A = x (ext), C = g_h1 ; mode 1: A = g_h1, C = g_h
template <int BM, int BN, int BK, int TM, int TN, bool RELU>
__global__ void sgemm(int M, int Nn, int K, const float* __restrict__ Aext,
                      const float* __restrict__ B, const float* __restrict__ bias,
                      int mode) {
    constexpr int NT = (BM / TM) * (BN / TN);
    const float* A = (mode == 0) ? Aext : g_h1;
    float* Cm = (mode == 0) ? g_h1 : g_h;

    __shared__ __align__(16) float As[BK][BM + 4];
    __shared__ __align__(16) float Bs[BK][BN];

    int tid = threadIdx.x;
    int brow = blockIdx.y, bcol = blockIdx.x;
    int tRow = tid / (BN / TN);
    int tCol = tid % (BN / TN);
    int m0 = brow * BM;

    float acc[TM][TN];
#pragma unroll
    for (int i = 0; i < TM; i++)
#pragma unroll
        for (int j = 0; j < TN; j++) acc[i][j] = 0.0f;

    for (int k0 = 0; k0 < K; k0 += BK) {
#pragma unroll
        for (int i = 0; i < (BM * BK) / NT; i++) {
            int idx = tid + i * NT;
            int m = idx / BK, kk = idx % BK;
            int gm = m0 + m;
            float v = (gm < M) ? A[(size_t)gm * K + k0 + kk] : 0.0f;
            As[kk][m] = v;
        }
#pragma unroll
        for (int i = 0; i < (BK * BN) / NT; i++) {
            int idx = tid + i * NT;
            int kk = idx / BN, n = idx % BN;
            Bs[kk][n] = B[(size_t)(k0 + kk) * Nn + bcol * BN + n];
        }
        __syncthreads();
#pragma unroll
        for (int kk = 0; kk < BK; kk++) {
            float rm[TM], rn[TN];
#pragma unroll
            for (int v4 = 0; v4 < TM / 4; v4++) {
                float4 t = *reinterpret_cast<const float4*>(&As[kk][tRow * TM + v4 * 4]);
                rm[v4 * 4 + 0] = t.x; rm[v4 * 4 + 1] = t.y;
                rm[v4 * 4 + 2] = t.z; rm[v4 * 4 + 3] = t.w;
            }
#pragma unroll
            for (int v4 = 0; v4 < TN / 4; v4++) {
                float4 t = *reinterpret_cast<const float4*>(&Bs[kk][tCol * TN + v4 * 4]);
                rn[v4 * 4 + 0] = t.x; rn[v4 * 4 + 1] = t.y;
                rn[v4 * 4 + 2] = t.z; rn[v4 * 4 + 3] = t.w;
            }
#pragma unroll
            for (int i = 0; i < TM; i++)
#pragma unroll
                for (int j = 0; j < TN; j++) acc[i][j] = fmaf(rm[i], rn[j], acc[i][j]);
        }
        __syncthreads();
    }

#pragma unroll
    for (int i = 0; i < TM; i++) {
        int gm = m0 + tRow * TM + i;
        if (gm < M) {
#pragma unroll
            for (int j = 0; j < TN; j++) {
                int gn = bcol * BN + tCol * TN + j;
                float v = acc[i][j] + bias[gn];
                if (RELU) v = fmaxf(v, 0.0f);
                Cm[(size_t)gm * Nn + gn] = v;
            }
        }
    }
}

// ---------------- propagation hop: warp per dst node, CSR gather ----------------
__global__ void k_hop(int hop, int N) {
    int gw = (blockIdx.x * blockDim.x + threadIdx.x) >> 5;
    int lane = threadIdx.x & 31;
    if (gw >= N) return;
    const float* __restrict__ zin = (hop == 0) ? g_h : ((hop & 1) ? g_zA : g_zB);
    float* __restrict__ zout = (hop & 1) ? g_zB : g_zA;

    int i = gw;
    float di = g_dinv[i];
    float selfw = (1.0f - F_ALPHA) * di * di;
    size_t base = (size_t)i * CC;
    float acc0 = selfw * zin[base + lane] + F_ALPHA * g_h[base + lane];
    float acc1 = selfw * zin[base + lane + 32] + F_ALPHA * g_h[base + lane + 32];

    int s0 = g_rowptr[i], s1 = g_rowptr[i + 1];
    for (int j = s0; j < s1; j++) {
        int s = g_esrc[j];
        float v = g_eval[j];
        size_t sb = (size_t)s * CC;
        acc0 = fmaf(v, zin[sb + lane], acc0);
        acc1 = fmaf(v, zin[sb + lane + 32], acc1);
    }
    zout[base + lane] = acc0;
    zout[base + lane + 32] = acc1;
}

// ---------------- outputs ----------------
// out[0:NC)   = log_softmax(z, axis=1)
// out[NC:2NC) = z
// out[2NC:3NC)= softmax(z, axis=0)

__global__ void k_rowsm(float* __restrict__ out, int N) {
    int gw = (blockIdx.x * blockDim.x + threadIdx.x) >> 5;
    int lane = threadIdx.x & 31;
    if (gw >= N) return;
    size_t base = (size_t)gw * CC;
    float v0 = g_zB[base + lane];
    float v1 = g_zB[base + lane + 32];
    float m = fmaxf(v0, v1);
#pragma unroll
    for (int off = 16; off > 0; off >>= 1)
        m = fmaxf(m, __shfl_xor_sync(0xffffffffu, m, off));
    float s = expf(v0 - m) + expf(v1 - m);
#pragma unroll
    for (int off = 16; off > 0; off >>= 1)
        s += __shfl_xor_sync(0xffffffffu, s, off);
    float ls = logf(s);
    size_t NCsz = (size_t)N * CC;
    out[base + lane] = v0 - m - ls;
    out[base + lane + 32] = v1 - m - ls;
    out[NCsz + base + lane] = v0;
    out[NCsz + base + lane + 32] = v1;
}

__device__ __forceinline__ unsigned encf(float x) {
    unsigned u = __float_as_uint(x);
    return (u & 0x80000000u) ? ~u : (u | 0x80000000u);
}

__global__ void k_colinit() {
    int c = threadIdx.x;
    if (c < CC) { g_colmax_enc[c] = 0u; g_colsum[c] = 0.0f; }
}

__global__ void k_colmax(int N) {
    int col = threadIdx.x & 63;
    int rg = threadIdx.x >> 6;  // 0..3
    float m = -3.4e38f;
    for (int r = blockIdx.x * 4 + rg; r < N; r += gridDim.x * 4)
        m = fmaxf(m, g_zB[(size_t)r * CC + col]);
    __shared__ float sm[256];
    sm[threadIdx.x] = m;
    __syncthreads();
    if (threadIdx.x < 128) sm[threadIdx.x] = fmaxf(sm[threadIdx.x], sm[threadIdx.x + 128]);
    __syncthreads();
    if (threadIdx.x < 64) {
        float mm = fmaxf(sm[threadIdx.x], sm[threadIdx.x + 64]);
        atomicMax(&g_colmax_enc[threadIdx.x], encf(mm));
    }
}

__global__ void k_coldec() {
    int c = threadIdx.x;
    if (c < CC) {
        unsigned e = g_colmax_enc[c];
        g_colmax[c] = (e & 0x80000000u) ? __uint_as_float(e & 0x7fffffffu)
                                        : __uint_as_float(~e);
    }
}

__global__ void k_colsum(int N) {
    int col = threadIdx.x & 63;
    int rg = threadIdx.x >> 6;
    float cm = g_colmax[col];
    float s = 0.0f;
    for (int r = blockIdx.x * 4 + rg; r < N; r += gridDim.x * 4)
        s += expf(g_zB[(size_t)r * CC + col] - cm);
    __shared__ float sm[256];
    sm[threadIdx.x] = s;
    __syncthreads();
    if (threadIdx.x < 128) sm[threadIdx.x] += sm[threadIdx.x + 128];
    __syncthreads();
    if (threadIdx.x < 64) {
        atomicAdd(&g_colsum[threadIdx.x], sm[threadIdx.x] + sm[threadIdx.x + 64]);
    }
}

__global__ void k_colout(float* __restrict__ out, int N) {
    size_t NCsz = (size_t)N * CC;
    for (size_t idx = blockIdx.x * blockDim.x + threadIdx.x; idx < NCsz;
         idx += (size_t)gridDim.x * blockDim.x) {
        int c = (int)(idx & 63);
        out[2 * NCsz + idx] = expf(g_zB[idx] - g_colmax[c]) / g_colsum[c];
    }
}

// ---------------- launch ----------------
extern "C" void kernel_launch(void* const* d_in, const int* in_sizes, int n_in,
                              void* d_out, int out_size) {
    const float* x = (const float*)d_in[0];
    const int* ei = (const int*)d_in[1];
    const float* W1 = (const float*)d_in[2];
    const float* b1 = (const float*)d_in[3];
    const float* W2 = (const float*)d_in[4];
    const float* b2 = (const float*)d_in[5];
    float* out = (float*)d_out;

    int N = in_sizes[0] / FF;
    int E = in_sizes[1] / 2;
    int NB = cdiv(N, 512);

    // preprocessing: degrees, dinv, CSR
    k_zero_deg<<<cdiv(N, 256), 256>>>(N);
    k_count<<<cdiv(E, 256), 256>>>(ei, E);
    k_dinv<<<cdiv(N, 256), 256>>>(N);
    k_chunksum<<<NB, 512>>>(N);
    k_scanchunks<<<1, 1>>>(NB);
    k_scan2<<<NB, 512>>>(N);
    k_scatter<<<cdiv(E, 256), 256>>>(ei, E);

    // MLP
    sgemm<128, 128, 8, 8, 8, true><<<dim3(HH / 128, cdiv(N, 128)), 256>>>(
        N, HH, FF, x, W1, b1, 0);
    sgemm<128, 64, 8, 8, 4, false><<<dim3(1, cdiv(N, 128)), 256>>>(
        N, CC, HH, x, W2, b2, 1);

    // 10 hops of APPNP propagation (final z lands in g_zB)
    int hop_blocks = cdiv(N, 8);  // 8 warps per 256-thread block
    for (int hop = 0; hop < K_HOPS; hop++) k_hop<<<hop_blocks, 256>>>(hop, N);

    // outputs
    k_rowsm<<<cdiv(N, 8), 256>>>(out, N);
    k_colinit<<<1, 64>>>();
    k_colmax<<<1024, 256>>>(N);
    k_coldec<<<1, 64>>>();
    k_colsum<<<1024, 256>>>(N);
    k_colout<<<cdiv(N * CC, 256), 256>>>(out, N);
}

// round 3
// speedup vs baseline: 1.0360x; 1.0360x over previous
#include <cuda_runtime.h>
#include <cuda_bf16.h>
#include <mma.h>
#include <math.h>

using namespace nvcuda;

// Problem constants (fixed shapes per reference setup_inputs)
constexpr int NN = 100000;   // nodes
constexpr int FF = 512;      // input features
constexpr int HH = 256;      // hidden
constexpr int CC = 64;       // classes
constexpr int EE = 3200000;  // edges
constexpr float F_ALPHA = 0.1f;
constexpr int K_HOPS = 10;

// ---------------- static device scratch (no allocs allowed) ----------------
__device__ int            g_degcnt[NN];
__device__ float          g_dinv[NN];
__device__ int            g_rowptr[NN + 1];
__device__ int            g_cursor[NN];
__device__ int            g_esrc[EE];
__device__ float          g_eval[EE];
__device__ __nv_bfloat16  g_h1hi[(size_t)NN * HH];
__device__ __nv_bfloat16  g_h1lo[(size_t)NN * HH];
__device__ float          g_h[(size_t)NN * CC];
__device__ float          g_zA[(size_t)NN * CC];
__device__ float          g_zB[(size_t)NN * CC];
__device__ unsigned       g_colmax_enc[CC];
__device__ float          g_colmax[CC];
__device__ float          g_colsum[CC];
__device__ int            g_chunksums[512];

static inline int cdiv(int a, int b) { return (a + b - 1) / b; }

// ---------------- graph preprocessing ----------------

__global__ void k_zero_deg(int N) {
    int i = blockIdx.x * blockDim.x + threadIdx.x;
    if (i < N) g_degcnt[i] = 0;
}

// count in-degree (by dst). edge_index is int32 [2, E].
__global__ void k_count(const int* __restrict__ ei, int E) {
    int e = blockIdx.x * blockDim.x + threadIdx.x;
    if (e < E) {
        int d = ei[E + e];
        atomicAdd(&g_degcnt[d], 1);
    }
}

__global__ void k_dinv(int N) {
    int i = blockIdx.x * blockDim.x + threadIdx.x;
    if (i < N) g_dinv[i] = rsqrtf((float)g_degcnt[i] + 1.0f);  // +1 self loop
}

// 3-kernel exclusive scan over degcnt -> rowptr (chunk = 512)
__global__ void k_chunksum(int N) {
    __shared__ int s[512];
    int i = blockIdx.x * 512 + threadIdx.x;
    s[threadIdx.x] = (i < N) ? g_degcnt[i] : 0;
    __syncthreads();
    for (int off = 256; off > 0; off >>= 1) {
        if (threadIdx.x < off) s[threadIdx.x] += s[threadIdx.x + off];
        __syncthreads();
    }
    if (threadIdx.x == 0) g_chunksums[blockIdx.x] = s[0];
}

__global__ void k_scanchunks(int NB) {
    int acc = 0;
    for (int b = 0; b < NB; b++) {
        int t = g_chunksums[b];
        g_chunksums[b] = acc;
        acc += t;
    }
}

__global__ void k_scan2(int N) {
    __shared__ int s[512];
    int i = blockIdx.x * 512 + threadIdx.x;
    int c = (i < N) ? g_degcnt[i] : 0;
    s[threadIdx.x] = c;
    __syncthreads();
    for (int off = 1; off < 512; off <<= 1) {
        int v = s[threadIdx.x];
        if (threadIdx.x >= off) v += s[threadIdx.x - off];
        __syncthreads();
        s[threadIdx.x] = v;
        __syncthreads();
    }
    int excl = s[threadIdx.x] - c + g_chunksums[blockIdx.x];
    if (i < N) {
        g_rowptr[i] = excl;
        g_cursor[i] = excl;
        if (i == N - 1) g_rowptr[N] = excl + c;
    }
}

// scatter edges into CSR (by dst), value = (1-alpha)*dinv[src]*dinv[dst]
__global__ void k_scatter(const int* __restrict__ ei, int E) {
    int e = blockIdx.x * blockDim.x + threadIdx.x;
    if (e < E) {
        int s = ei[e];
        int d = ei[E + e];
        int pos = atomicAdd(&g_cursor[d], 1);
        g_esrc[pos] = s;
        g_eval[pos] = (1.0f - F_ALPHA) * g_dinv[s] * g_dinv[d];
    }
}

// ---------------- bf16x3 split helpers ----------------
__device__ __forceinline__ void split_bf16(float v, __nv_bfloat16& hi, __nv_bfloat16& lo) {
    hi = __float2bfloat16(v);
    lo = __float2bfloat16(v - __bfloat162float(hi));
}

// ---------------- GEMM1: h1 = relu(x @ W1 + b1), bf16x3 tensor path ----------------
// CTA tile 128x256 (full N), BK=32, 16 warps, warp tile 32x64.
// Writes h1 as bf16 hi/lo pair (inputs for GEMM2, no reconversion).
__global__ __launch_bounds__(512) void k_gemm1(const float* __restrict__ A,
                                               const float* __restrict__ B,
                                               const float* __restrict__ bias, int M) {
    constexpr int BM = 128, BN = 256, BK = 32, KK = FF;
    // 24576 bf16 = 49152 bytes (exactly 48KB static smem)
    __shared__ __align__(16) __nv_bfloat16 sm[BM * BK * 2 + BK * BN * 2];
    __nv_bfloat16* Ash = sm;
    __nv_bfloat16* Asl = sm + BM * BK;
    __nv_bfloat16* Bsh = sm + BM * BK * 2;
    __nv_bfloat16* Bsl = Bsh + BK * BN;

    int tid = threadIdx.x;
    int warp = tid >> 5, lane = tid & 31;
    int wm = warp >> 2;   // 0..3 (rows of 32)
    int wn = warp & 3;    // 0..3 (cols of 64)
    int m0 = blockIdx.x * BM;

    wmma::fragment<wmma::accumulator, 16, 16, 16, float> acc[2][4];
#pragma unroll
    for (int i = 0; i < 2; i++)
#pragma unroll
        for (int j = 0; j < 4; j++) wmma::fill_fragment(acc[i][j], 0.0f);

    for (int k0 = 0; k0 < KK; k0 += BK) {
        // load A tile 128x32 fp32 -> split bf16 (1024 float4, 2 per thread)
#pragma unroll
        for (int i = 0; i < 2; i++) {
            int f4 = tid + i * 512;
            int r = f4 >> 3;        // 8 float4 per row
            int c4 = (f4 & 7) * 4;
            int gm = m0 + r;
            float4 v = make_float4(0.f, 0.f, 0.f, 0.f);
            if (gm < M) v = *(const float4*)&A[(size_t)gm * KK + k0 + c4];
            __nv_bfloat16 h0, l0, h1_, l1, h2, l2, h3, l3;
            split_bf16(v.x, h0, l0); split_bf16(v.y, h1_, l1);
            split_bf16(v.z, h2, l2); split_bf16(v.w, h3, l3);
            int o = r * BK + c4;
            Ash[o] = h0; Ash[o + 1] = h1_; Ash[o + 2] = h2; Ash[o + 3] = h3;
            Asl[o] = l0; Asl[o + 1] = l1; Asl[o + 2] = l2; Asl[o + 3] = l3;
        }
        // load B tile 32x256 fp32 -> split (2048 float4, 4 per thread)
#pragma unroll
        for (int i = 0; i < 4; i++) {
            int f4 = tid + i * 512;
            int r = f4 >> 6;        // 64 float4 per row
            int c4 = (f4 & 63) * 4;
            float4 v = *(const float4*)&B[(size_t)(k0 + r) * BN + c4];
            __nv_bfloat16 h0, l0, h1_, l1, h2, l2, h3, l3;
            split_bf16(v.x, h0, l0); split_bf16(v.y, h1_, l1);
            split_bf16(v.z, h2, l2); split_bf16(v.w, h3, l3);
            int o = r * BN + c4;
            Bsh[o] = h0; Bsh[o + 1] = h1_; Bsh[o + 2] = h2; Bsh[o + 3] = h3;
            Bsl[o] = l0; Bsl[o + 1] = l1; Bsl[o + 2] = l2; Bsl[o + 3] = l3;
        }
        __syncthreads();

#pragma unroll
        for (int kk = 0; kk < BK; kk += 16) {
            wmma::fragment<wmma::matrix_a, 16, 16, 16, __nv_bfloat16, wmma::row_major> ah[2], al[2];
#pragma unroll
            for (int i = 0; i < 2; i++) {
                wmma::load_matrix_sync(ah[i], Ash + (wm * 32 + i * 16) * BK + kk, BK);
                wmma::load_matrix_sync(al[i], Asl + (wm * 32 + i * 16) * BK + kk, BK);
            }
#pragma unroll
            for (int j = 0; j < 4; j++) {
                wmma::fragment<wmma::matrix_b, 16, 16, 16, __nv_bfloat16, wmma::row_major> bh, bl;
                wmma::load_matrix_sync(bh, Bsh + kk * BN + wn * 64 + j * 16, BN);
                wmma::load_matrix_sync(bl, Bsl + kk * BN + wn * 64 + j * 16, BN);
#pragma unroll
                for (int i = 0; i < 2; i++) {
                    wmma::mma_sync(acc[i][j], ah[i], bh, acc[i][j]);
                    wmma::mma_sync(acc[i][j], al[i], bh, acc[i][j]);
                    wmma::mma_sync(acc[i][j], ah[i], bl, acc[i][j]);
                }
            }
        }
        __syncthreads();
    }

    // epilogue: bias + relu + split to bf16 hi/lo; stage via smem (aliased)
    float* ws = (float*)sm + warp * 256;
#pragma unroll
    for (int i = 0; i < 2; i++)
#pragma unroll
        for (int j = 0; j < 4; j++) {
            wmma::store_matrix_sync(ws, acc[i][j], 16, wmma::mem_row_major);
            __syncwarp();
#pragma unroll
            for (int t = 0; t < 8; t++) {
                int idx = lane + t * 32;
                int r = idx >> 4, c = idx & 15;
                int gm = m0 + wm * 32 + i * 16 + r;
                int gn = wn * 64 + j * 16 + c;
                if (gm < M) {
                    float v = fmaxf(ws[idx] + bias[gn], 0.0f);
                    __nv_bfloat16 hi, lo;
                    split_bf16(v, hi, lo);
                    g_h1hi[(size_t)gm * HH + gn] = hi;
                    g_h1lo[(size_t)gm * HH + gn] = lo;
                }
            }
            __syncwarp();
        }
}

// ---------------- GEMM2: h = h1 @ W2 + b2 (bf16x3, A already split) ----------------
// CTA tile 128x64, BK=32, 8 warps, warp tile 32x32.
__global__ __launch_bounds__(256) void k_gemm2(const float* __restrict__ B,
                                               const float* __restrict__ bias, int M) {
    constexpr int BM = 128, BN = 64, BK = 32, KK = HH;
    __shared__ __align__(16) __nv_bfloat16 sm[BM * BK * 2 + BK * BN * 2];  // 24KB
    __nv_bfloat16* Ash = sm;
    __nv_bfloat16* Asl = sm + BM * BK;
    __nv_bfloat16* Bsh = sm + BM * BK * 2;
    __nv_bfloat16* Bsl = Bsh + BK * BN;

    int tid = threadIdx.x;
    int warp = tid >> 5, lane = tid & 31;
    int wm = warp >> 1;   // 0..3
    int wn = warp & 1;    // 0..1
    int m0 = blockIdx.x * BM;

    wmma::fragment<wmma::accumulator, 16, 16, 16, float> acc[2][2];
#pragma unroll
    for (int i = 0; i < 2; i++)
#pragma unroll
        for (int j = 0; j < 2; j++) wmma::fill_fragment(acc[i][j], 0.0f);

    for (int k0 = 0; k0 < KK; k0 += BK) {
        // A tiles: bf16 hi/lo direct loads (4096 bf16 each = 512 uint4 per array)
#pragma unroll
        for (int i = 0; i < 2; i++) {
            int u4 = tid + i * 256;
            int r = u4 >> 2;          // 4 uint4 per row (32 bf16)
            int c8 = (u4 & 3) * 8;
            int gm = m0 + r;
            uint4 vh = make_uint4(0, 0, 0, 0), vl = make_uint4(0, 0, 0, 0);
            if (gm < M) {
                vh = *(const uint4*)&g_h1hi[(size_t)gm * KK + k0 + c8];
                vl = *(const uint4*)&g_h1lo[(size_t)gm * KK + k0 + c8];
            }
            *(uint4*)&Ash[r * BK + c8] = vh;
            *(uint4*)&Asl[r * BK + c8] = vl;
        }
        // B tile 32x64 fp32 -> split (512 float4, 2 per thread)
#pragma unroll
        for (int i = 0; i < 2; i++) {
            int f4 = tid + i * 256;
            int r = f4 >> 4;          // 16 float4 per row
            int c4 = (f4 & 15) * 4;
            float4 v = *(const float4*)&B[(size_t)(k0 + r) * BN + c4];
            __nv_bfloat16 h0, l0, h1_, l1, h2, l2, h3, l3;
            split_bf16(v.x, h0, l0); split_bf16(v.y, h1_, l1);
            split_bf16(v.z, h2, l2); split_bf16(v.w, h3, l3);
            int o = r * BN + c4;
            Bsh[o] = h0; Bsh[o + 1] = h1_; Bsh[o + 2] = h2; Bsh[o + 3] = h3;
            Bsl[o] = l0; Bsl[o + 1] = l1; Bsl[o + 2] = l2; Bsl[o + 3] = l3;
        }
        __syncthreads();

#pragma unroll
        for (int kk = 0; kk < BK; kk += 16) {
            wmma::fragment<wmma::matrix_a, 16, 16, 16, __nv_bfloat16, wmma::row_major> ah[2], al[2];
#pragma unroll
            for (int i = 0; i < 2; i++) {
                wmma::load_matrix_sync(ah[i], Ash + (wm * 32 + i * 16) * BK + kk, BK);
                wmma::load_matrix_sync(al[i], Asl + (wm * 32 + i * 16) * BK + kk, BK);
            }
#pragma unroll
            for (int j = 0; j < 2; j++) {
                wmma::fragment<wmma::matrix_b, 16, 16, 16, __nv_bfloat16, wmma::row_major> bh, bl;
                wmma::load_matrix_sync(bh, Bsh + kk * BN + wn * 32 + j * 16, BN);
                wmma::load_matrix_sync(bl, Bsl + kk * BN + wn * 32 + j * 16, BN);
#pragma unroll
                for (int i = 0; i < 2; i++) {
                    wmma::mma_sync(acc[i][j], ah[i], bh, acc[i][j]);
                    wmma::mma_sync(acc[i][j], al[i], bh, acc[i][j]);
                    wmma::mma_sync(acc[i][j], ah[i], bl, acc[i][j]);
                }
            }
        }
        __syncthreads();
    }

    // epilogue: bias, fp32 out to g_h
    float* ws = (float*)sm + warp * 256;
#pragma unroll
    for (int i = 0; i < 2; i++)
#pragma unroll
        for (int j = 0; j < 2; j++) {
            wmma::store_matrix_sync(ws, acc[i][j], 16, wmma::mem_row_major);
            __syncwarp();
#pragma unroll
            for (int t = 0; t < 8; t++) {
                int idx = lane + t * 32;
                int r = idx >> 4, c = idx & 15;
                int gm = m0 + wm * 32 + i * 16 + r;
                int gn = wn * 32 + j * 16 + c;
                if (gm < M)
                    g_h[(size_t)gm * BN + gn] = ws[idx] + bias[gn];
            }
            __syncwarp();
        }
}

// ---------------- propagation hop: warp per dst node, CSR gather ----------------
__global__ void k_hop(int hop, int N) {
    int gw = (blockIdx.x * blockDim.x + threadIdx.x) >> 5;
    int lane = threadIdx.x & 31;
    if (gw >= N) return;
    const float* __restrict__ zin = (hop == 0) ? g_h : ((hop & 1) ? g_zA : g_zB);
    float* __restrict__ zout = (hop & 1) ? g_zB : g_zA;

    int i = gw;
    float di = g_dinv[i];
    float selfw = (1.0f - F_ALPHA) * di * di;
    size_t base = (size_t)i * CC;
    float acc0 = selfw * zin[base + lane] + F_ALPHA * g_h[base + lane];
    float acc1 = selfw * zin[base + lane + 32] + F_ALPHA * g_h[base + lane + 32];

    int s0 = g_rowptr[i], s1 = g_rowptr[i + 1];
    for (int j = s0; j < s1; j++) {
        int s = g_esrc[j];
        float v = g_eval[j];
        size_t sb = (size_t)s * CC;
        acc0 = fmaf(v, zin[sb + lane], acc0);
        acc1 = fmaf(v, zin[sb + lane + 32], acc1);
    }
    zout[base + lane] = acc0;
    zout[base + lane + 32] = acc1;
}

// ---------------- outputs ----------------
__global__ void k_rowsm(float* __restrict__ out, int N) {
    int gw = (blockIdx.x * blockDim.x + threadIdx.x) >> 5;
    int lane = threadIdx.x & 31;
    if (gw >= N) return;
    size_t base = (size_t)gw * CC;
    float v0 = g_zB[base + lane];
    float v1 = g_zB[base + lane + 32];
    float m = fmaxf(v0, v1);
#pragma unroll
    for (int off = 16; off > 0; off >>= 1)
        m = fmaxf(m, __shfl_xor_sync(0xffffffffu, m, off));
    float s = expf(v0 - m) + expf(v1 - m);
#pragma unroll
    for (int off = 16; off > 0; off >>= 1)
        s += __shfl_xor_sync(0xffffffffu, s, off);
    float ls = logf(s);
    size_t NCsz = (size_t)N * CC;
    out[base + lane] = v0 - m - ls;
    out[base + lane + 32] = v1 - m - ls;
    out[NCsz + base + lane] = v0;
    out[NCsz + base + lane + 32] = v1;
}

__device__ __forceinline__ unsigned encf(float x) {
    unsigned u = __float_as_uint(x);
    return (u & 0x80000000u) ? ~u : (u | 0x80000000u);
}

__global__ void k_colinit() {
    int c = threadIdx.x;
    if (c < CC) { g_colmax_enc[c] = 0u; g_colsum[c] = 0.0f; }
}

__global__ void k_colmax(int N) {
    int col = threadIdx.x & 63;
    int rg = threadIdx.x >> 6;
    float m = -3.4e38f;
    for (int r = blockIdx.x * 4 + rg; r < N; r += gridDim.x * 4)
        m = fmaxf(m, g_zB[(size_t)r * CC + col]);
    __shared__ float sm[256];
    sm[threadIdx.x] = m;
    __syncthreads();
    if (threadIdx.x < 128) sm[threadIdx.x] = fmaxf(sm[threadIdx.x], sm[threadIdx.x + 128]);
    __syncthreads();
    if (threadIdx.x < 64) {
        float mm = fmaxf(sm[threadIdx.x], sm[threadIdx.x + 64]);
        atomicMax(&g_colmax_enc[threadIdx.x], encf(mm));
    }
}

__global__ void k_coldec() {
    int c = threadIdx.x;
    if (c < CC) {
        unsigned e = g_colmax_enc[c];
        g_colmax[c] = (e & 0x80000000u) ? __uint_as_float(e & 0x7fffffffu)
                                        : __uint_as_float(~e);
    }
}

__global__ void k_colsum(int N) {
    int col = threadIdx.x & 63;
    int rg = threadIdx.x >> 6;
    float cm = g_colmax[col];
    float s = 0.0f;
    for (int r = blockIdx.x * 4 + rg; r < N; r += gridDim.x * 4)
        s += expf(g_zB[(size_t)r * CC + col] - cm);
    __shared__ float sm[256];
    sm[threadIdx.x] = s;
    __syncthreads();
    if (threadIdx.x < 128) sm[threadIdx.x] += sm[threadIdx.x + 128];
    __syncthreads();
    if (threadIdx.x < 64) {
        atomicAdd(&g_colsum[threadIdx.x], sm[threadIdx.x] + sm[threadIdx.x + 64]);
    }
}

__global__ void k_colout(float* __restrict__ out, int N) {
    size_t NCsz = (size_t)N * CC;
    for (size_t idx = blockIdx.x * blockDim.x + threadIdx.x; idx < NCsz;
         idx += (size_t)gridDim.x * blockDim.x) {
        int c = (int)(idx & 63);
        out[2 * NCsz + idx] = expf(g_zB[idx] - g_colmax[c]) / g_colsum[c];
    }
}

// ---------------- launch ----------------
extern "C" void kernel_launch(void* const* d_in, const int* in_sizes, int n_in,
                              void* d_out, int out_size) {
    const float* x = (const float*)d_in[0];
    const int* ei = (const int*)d_in[1];
    const float* W1 = (const float*)d_in[2];
    const float* b1 = (const float*)d_in[3];
    const float* W2 = (const float*)d_in[4];
    const float* b2 = (const float*)d_in[5];
    float* out = (float*)d_out;

    int N = in_sizes[0] / FF;
    int E = in_sizes[1] / 2;
    int NB = cdiv(N, 512);

    // preprocessing: degrees, dinv, CSR
    k_zero_deg<<<cdiv(N, 256), 256>>>(N);
    k_count<<<cdiv(E, 256), 256>>>(ei, E);
    k_dinv<<<cdiv(N, 256), 256>>>(N);
    k_chunksum<<<NB, 512>>>(N);
    k_scanchunks<<<1, 1>>>(NB);
    k_scan2<<<NB, 512>>>(N);
    k_scatter<<<cdiv(E, 256), 256>>>(ei, E);

    // MLP (bf16x3 tensor-core path)
    k_gemm1<<<cdiv(N, 128), 512>>>(x, W1, b1, N);
    k_gemm2<<<cdiv(N, 128), 256>>>(W2, b2, N);

    // 10 hops of APPNP propagation (final z lands in g_zB)
    int hop_blocks = cdiv(N, 8);
    for (int hop = 0; hop < K_HOPS; hop++) k_hop<<<hop_blocks, 256>>>(hop, N);

    // outputs
    k_rowsm<<<cdiv(N, 8), 256>>>(out, N);
    k_colinit<<<1, 64>>>();
    k_colmax<<<1024, 256>>>(N);
    k_coldec<<<1, 64>>>();
    k_colsum<<<1024, 256>>>(N);
    k_colout<<<cdiv(N * CC, 256), 256>>>(out, N);
}

// round 8
// speedup vs baseline: 1.1525x; 1.1125x over previous
#include <cuda_runtime.h>
#include <cuda_bf16.h>
#include <mma.h>
#include <math.h>

using namespace nvcuda;

constexpr int NN = 100000;   // nodes
constexpr int FF = 512;      // input features
constexpr int HH = 256;      // hidden
constexpr int CC = 64;       // classes
constexpr int EE = 3200000;  // edges
constexpr int K_HOPS = 10;

// ---------------- static device scratch ----------------
__device__ int            g_degcnt[NN];
__device__ float          g_dinv[NN];
__device__ float          g_c0[NN];          // 0.9/(deg+1)
__device__ int            g_rowptr[NN + 1];
__device__ int            g_cursor[NN];
__device__ int            g_esrc[EE];
__device__ __nv_bfloat16  g_h1hi[(size_t)NN * HH];
__device__ __nv_bfloat16  g_h1lo[(size_t)NN * HH];
__device__ float          g_h[(size_t)NN * CC];    // MLP output
__device__ float          g_ah[(size_t)NN * CC];   // 0.1 * dinv * h
__device__ float          g_yA[(size_t)NN * CC];   // fp32 propagation state
__device__ float          g_yB[(size_t)NN * CC];
__device__ float          g_z[(size_t)NN * CC];    // final z
__device__ float          g_colsum[CC];
__device__ int            g_chunksums[256];

static inline int cdiv(int a, int b) { return (a + b - 1) / b; }

// ---------------- graph preprocessing ----------------
__global__ void k_zero_deg(int N) {
    int i = blockIdx.x * blockDim.x + threadIdx.x;
    if (i < N) g_degcnt[i] = 0;
    if (i < CC) g_colsum[i] = 0.0f;
}

__global__ void k_count(const int* __restrict__ ei, int E) {
    int e = blockIdx.x * blockDim.x + threadIdx.x;
    if (e < E) atomicAdd(&g_degcnt[ei[E + e]], 1);
}

// per-chunk sums (512 wide) + dinv/c0 fused
__global__ void k_chunksum(int N) {
    __shared__ int s[512];
    int i = blockIdx.x * 512 + threadIdx.x;
    int c = (i < N) ? g_degcnt[i] : 0;
    if (i < N) {
        float d1 = (float)c + 1.0f;       // +1 self loop
        g_dinv[i] = rsqrtf(d1);
        g_c0[i] = 0.9f / d1;
    }
    s[threadIdx.x] = c;
    __syncthreads();
    for (int off = 256; off > 0; off >>= 1) {
        if (threadIdx.x < off) s[threadIdx.x] += s[threadIdx.x + off];
        __syncthreads();
    }
    if (threadIdx.x == 0) g_chunksums[blockIdx.x] = s[0];
}

// exclusive scan, with chunk prefix computed in-block (NB <= 256)
__global__ void k_scan2(int N, int NB) {
    __shared__ int s[512];
    __shared__ int cs[256];
    int i = blockIdx.x * 512 + threadIdx.x;
    int c = (i < N) ? g_degcnt[i] : 0;
    if (threadIdx.x < 256)
        cs[threadIdx.x] = (threadIdx.x < blockIdx.x && threadIdx.x < NB)
                              ? g_chunksums[threadIdx.x] : 0;
    s[threadIdx.x] = c;
    __syncthreads();
    for (int off = 128; off > 0; off >>= 1) {
        if (threadIdx.x < off) cs[threadIdx.x] += cs[threadIdx.x + off];
        __syncthreads();
    }
    for (int off = 1; off < 512; off <<= 1) {
        int v = s[threadIdx.x];
        if (threadIdx.x >= off) v += s[threadIdx.x - off];
        __syncthreads();
        s[threadIdx.x] = v;
        __syncthreads();
    }
    int excl = s[threadIdx.x] - c + cs[0];
    if (i < N) {
        g_rowptr[i] = excl;
        g_cursor[i] = excl;
        if (i == N - 1) g_rowptr[N] = excl + c;
    }
}

__global__ void k_scatter(const int* __restrict__ ei, int E) {
    int e = blockIdx.x * blockDim.x + threadIdx.x;
    if (e < E) {
        int s = ei[e];
        int d = ei[E + e];
        int pos = atomicAdd(&g_cursor[d], 1);
        g_esrc[pos] = s;
    }
}

// ---------------- bf16x3 split helper ----------------
__device__ __forceinline__ void split_bf16(float v, __nv_bfloat16& hi, __nv_bfloat16& lo) {
    hi = __float2bfloat16(v);
    lo = __float2bfloat16(v - __bfloat162float(hi));
}

// ---------------- GEMM1: h1 = relu(x @ W1 + b1), bf16x3 tensor path ----------------
__global__ __launch_bounds__(512) void k_gemm1(const float* __restrict__ A,
                                               const float* __restrict__ B,
                                               const float* __restrict__ bias, int M) {
    constexpr int BM = 128, BN = 256, BK = 32, KK = FF;
    __shared__ __align__(16) __nv_bfloat16 sm[BM * BK * 2 + BK * BN * 2];
    __nv_bfloat16* Ash = sm;
    __nv_bfloat16* Asl = sm + BM * BK;
    __nv_bfloat16* Bsh = sm + BM * BK * 2;
    __nv_bfloat16* Bsl = Bsh + BK * BN;

    int tid = threadIdx.x;
    int warp = tid >> 5, lane = tid & 31;
    int wm = warp >> 2;
    int wn = warp & 3;
    int m0 = blockIdx.x * BM;

    wmma::fragment<wmma::accumulator, 16, 16, 16, float> acc[2][4];
#pragma unroll
    for (int i = 0; i < 2; i++)
#pragma unroll
        for (int j = 0; j < 4; j++) wmma::fill_fragment(acc[i][j], 0.0f);

    for (int k0 = 0; k0 < KK; k0 += BK) {
#pragma unroll
        for (int i = 0; i < 2; i++) {
            int f4 = tid + i * 512;
            int r = f4 >> 3;
            int c4 = (f4 & 7) * 4;
            int gm = m0 + r;
            float4 v = make_float4(0.f, 0.f, 0.f, 0.f);
            if (gm < M) v = *(const float4*)&A[(size_t)gm * KK + k0 + c4];
            __nv_bfloat16 h0, l0, h1_, l1, h2, l2, h3, l3;
            split_bf16(v.x, h0, l0); split_bf16(v.y, h1_, l1);
            split_bf16(v.z, h2, l2); split_bf16(v.w, h3, l3);
            int o = r * BK + c4;
            Ash[o] = h0; Ash[o + 1] = h1_; Ash[o + 2] = h2; Ash[o + 3] = h3;
            Asl[o] = l0; Asl[o + 1] = l1; Asl[o + 2] = l2; Asl[o + 3] = l3;
        }
#pragma unroll
        for (int i = 0; i < 4; i++) {
            int f4 = tid + i * 512;
            int r = f4 >> 6;
            int c4 = (f4 & 63) * 4;
            float4 v = *(const float4*)&B[(size_t)(k0 + r) * BN + c4];
            __nv_bfloat16 h0, l0, h1_, l1, h2, l2, h3, l3;
            split_bf16(v.x, h0, l0); split_bf16(v.y, h1_, l1);
            split_bf16(v.z, h2, l2); split_bf16(v.w, h3, l3);
            int o = r * BN + c4;
            Bsh[o] = h0; Bsh[o + 1] = h1_; Bsh[o + 2] = h2; Bsh[o + 3] = h3;
            Bsl[o] = l0; Bsl[o + 1] = l1; Bsl[o + 2] = l2; Bsl[o + 3] = l3;
        }
        __syncthreads();

#pragma unroll
        for (int kk = 0; kk < BK; kk += 16) {
            wmma::fragment<wmma::matrix_a, 16, 16, 16, __nv_bfloat16, wmma::row_major> ah[2], al[2];
#pragma unroll
            for (int i = 0; i < 2; i++) {
                wmma::load_matrix_sync(ah[i], Ash + (wm * 32 + i * 16) * BK + kk, BK);
                wmma::load_matrix_sync(al[i], Asl + (wm * 32 + i * 16) * BK + kk, BK);
            }
#pragma unroll
            for (int j = 0; j < 4; j++) {
                wmma::fragment<wmma::matrix_b, 16, 16, 16, __nv_bfloat16, wmma::row_major> bh, bl;
                wmma::load_matrix_sync(bh, Bsh + kk * BN + wn * 64 + j * 16, BN);
                wmma::load_matrix_sync(bl, Bsl + kk * BN + wn * 64 + j * 16, BN);
#pragma unroll
                for (int i = 0; i < 2; i++) {
                    wmma::mma_sync(acc[i][j], ah[i], bh, acc[i][j]);
                    wmma::mma_sync(acc[i][j], al[i], bh, acc[i][j]);
                    wmma::mma_sync(acc[i][j], ah[i], bl, acc[i][j]);
                }
            }
        }
        __syncthreads();
    }

    float* ws = (float*)sm + warp * 256;
#pragma unroll
    for (int i = 0; i < 2; i++)
#pragma unroll
        for (int j = 0; j < 4; j++) {
            wmma::store_matrix_sync(ws, acc[i][j], 16, wmma::mem_row_major);
            __syncwarp();
#pragma unroll
            for (int t = 0; t < 8; t++) {
                int idx = lane + t * 32;
                int r = idx >> 4, c = idx & 15;
                int gm = m0 + wm * 32 + i * 16 + r;
                int gn = wn * 64 + j * 16 + c;
                if (gm < M) {
                    float v = fmaxf(ws[idx] + bias[gn], 0.0f);
                    __nv_bfloat16 hi, lo;
                    split_bf16(v, hi, lo);
                    g_h1hi[(size_t)gm * HH + gn] = hi;
                    g_h1lo[(size_t)gm * HH + gn] = lo;
                }
            }
            __syncwarp();
        }
}

// ---------------- GEMM2: h = h1 @ W2 + b2; epilogue also emits y0 & ah ------------
__global__ __launch_bounds__(256) void k_gemm2(const float* __restrict__ B,
                                               const float* __restrict__ bias, int M) {
    constexpr int BM = 128, BN = 64, BK = 32, KK = HH;
    __shared__ __align__(16) __nv_bfloat16 sm[BM * BK * 2 + BK * BN * 2];
    __nv_bfloat16* Ash = sm;
    __nv_bfloat16* Asl = sm + BM * BK;
    __nv_bfloat16* Bsh = sm + BM * BK * 2;
    __nv_bfloat16* Bsl = Bsh + BK * BN;

    int tid = threadIdx.x;
    int warp = tid >> 5, lane = tid & 31;
    int wm = warp >> 1;
    int wn = warp & 1;
    int m0 = blockIdx.x * BM;

    wmma::fragment<wmma::accumulator, 16, 16, 16, float> acc[2][2];
#pragma unroll
    for (int i = 0; i < 2; i++)
#pragma unroll
        for (int j = 0; j < 2; j++) wmma::fill_fragment(acc[i][j], 0.0f);

    for (int k0 = 0; k0 < KK; k0 += BK) {
#pragma unroll
        for (int i = 0; i < 2; i++) {
            int u4 = tid + i * 256;
            int r = u4 >> 2;
            int c8 = (u4 & 3) * 8;
            int gm = m0 + r;
            uint4 vh = make_uint4(0, 0, 0, 0), vl = make_uint4(0, 0, 0, 0);
            if (gm < M) {
                vh = *(const uint4*)&g_h1hi[(size_t)gm * KK + k0 + c8];
                vl = *(const uint4*)&g_h1lo[(size_t)gm * KK + k0 + c8];
            }
            *(uint4*)&Ash[r * BK + c8] = vh;
            *(uint4*)&Asl[r * BK + c8] = vl;
        }
#pragma unroll
        for (int i = 0; i < 2; i++) {
            int f4 = tid + i * 256;
            int r = f4 >> 4;
            int c4 = (f4 & 15) * 4;
            float4 v = *(const float4*)&B[(size_t)(k0 + r) * BN + c4];
            __nv_bfloat16 h0, l0, h1_, l1, h2, l2, h3, l3;
            split_bf16(v.x, h0, l0); split_bf16(v.y, h1_, l1);
            split_bf16(v.z, h2, l2); split_bf16(v.w, h3, l3);
            int o = r * BN + c4;
            Bsh[o] = h0; Bsh[o + 1] = h1_; Bsh[o + 2] = h2; Bsh[o + 3] = h3;
            Bsl[o] = l0; Bsl[o + 1] = l1; Bsl[o + 2] = l2; Bsl[o + 3] = l3;
        }
        __syncthreads();

#pragma unroll
        for (int kk = 0; kk < BK; kk += 16) {
            wmma::fragment<wmma::matrix_a, 16, 16, 16, __nv_bfloat16, wmma::row_major> ah[2], al[2];
#pragma unroll
            for (int i = 0; i < 2; i++) {
                wmma::load_matrix_sync(ah[i], Ash + (wm * 32 + i * 16) * BK + kk, BK);
                wmma::load_matrix_sync(al[i], Asl + (wm * 32 + i * 16) * BK + kk, BK);
            }
#pragma unroll
            for (int j = 0; j < 2; j++) {
                wmma::fragment<wmma::matrix_b, 16, 16, 16, __nv_bfloat16, wmma::row_major> bh, bl;
                wmma::load_matrix_sync(bh, Bsh + kk * BN + wn * 32 + j * 16, BN);
                wmma::load_matrix_sync(bl, Bsl + kk * BN + wn * 32 + j * 16, BN);
#pragma unroll
                for (int i = 0; i < 2; i++) {
                    wmma::mma_sync(acc[i][j], ah[i], bh, acc[i][j]);
                    wmma::mma_sync(acc[i][j], al[i], bh, acc[i][j]);
                    wmma::mma_sync(acc[i][j], ah[i], bl, acc[i][j]);
                }
            }
        }
        __syncthreads();
    }

    float* ws = (float*)sm + warp * 256;
#pragma unroll
    for (int i = 0; i < 2; i++)
#pragma unroll
        for (int j = 0; j < 2; j++) {
            wmma::store_matrix_sync(ws, acc[i][j], 16, wmma::mem_row_major);
            __syncwarp();
#pragma unroll
            for (int t = 0; t < 8; t++) {
                int idx = lane + t * 32;
                int r = idx >> 4, c = idx & 15;
                int gm = m0 + wm * 32 + i * 16 + r;
                int gn = wn * 32 + j * 16 + c;
                if (gm < M) {
                    float v = ws[idx] + bias[gn];
                    float di = g_dinv[gm];
                    size_t o = (size_t)gm * BN + gn;
                    g_h[o] = v;
                    g_yA[o] = di * v;          // y0 = dinv * h
                    g_ah[o] = 0.1f * di * v;   // alpha * dinv * h
                }
            }
            __syncwarp();
        }
}

// ---------------- hop: warp per node, fp32 float2 lanes ----------------
// ping-pong buffers selected IN DEVICE CODE (passing __device__ symbols from
// host gives the host shadow address — silently readable via ATS on GB300,
// which was the round-4/7 correctness bug).
__global__ void k_hopf(int hop, int N) {
    const float2* __restrict__ yin =
        (hop & 1) ? (const float2*)g_yB : (const float2*)g_yA;
    float2* __restrict__ yout = (hop & 1) ? (float2*)g_yA : (float2*)g_yB;

    int gw = (blockIdx.x * blockDim.x + threadIdx.x) >> 5;
    int lane = threadIdx.x & 31;
    if (gw >= N) return;
    int off = gw * 32 + lane;
    float2 w = yin[off];                         // self loop
    float acc0 = w.x, acc1 = w.y;
    int s0 = g_rowptr[gw], s1 = g_rowptr[gw + 1];
#pragma unroll 4
    for (int j = s0; j < s1; j++) {
        float2 v = __ldg(&yin[(size_t)__ldg(&g_esrc[j]) * 32 + lane]);
        acc0 += v.x;
        acc1 += v.y;
    }
    float c0 = g_c0[gw];
    float2 a = ((const float2*)g_ah)[off];
    yout[off] = make_float2(fmaf(c0, acc0, a.x), fmaf(c0, acc1, a.y));
}

// last hop: reads g_yB (state after 9 hops), emits fp32 z = 0.9*dinv*acc + 0.1*h
__global__ void k_hoplast(int N) {
    const float2* __restrict__ yin = (const float2*)g_yB;
    int gw = (blockIdx.x * blockDim.x + threadIdx.x) >> 5;
    int lane = threadIdx.x & 31;
    if (gw >= N) return;
    int off = gw * 32 + lane;
    float2 w = yin[off];
    float acc0 = w.x, acc1 = w.y;
    int s0 = g_rowptr[gw], s1 = g_rowptr[gw + 1];
#pragma unroll 4
    for (int j = s0; j < s1; j++) {
        float2 v = __ldg(&yin[(size_t)__ldg(&g_esrc[j]) * 32 + lane]);
        acc0 += v.x;
        acc1 += v.y;
    }
    float s = 0.9f * g_dinv[gw];
    float2 h2 = ((const float2*)g_h)[off];
    ((float2*)g_z)[off] =
        make_float2(fmaf(s, acc0, 0.1f * h2.x), fmaf(s, acc1, 0.1f * h2.y));
}

// ---------------- outputs ----------------
// out[0:NC) = log_softmax(z,1); out[NC:2NC) = z; column exp-sums accumulated here.
__global__ void k_rowsm(float* __restrict__ out, int N) {
    __shared__ float colacc[CC];
    int tid = threadIdx.x;
    if (tid < CC) colacc[tid] = 0.0f;
    __syncthreads();
    int warp = tid >> 5, lane = tid & 31;
    size_t NCsz = (size_t)N * CC;
    for (int node = blockIdx.x * 8 + warp; node < N; node += gridDim.x * 8) {
        size_t base = (size_t)node * CC;
        float v0 = g_z[base + lane];
        float v1 = g_z[base + lane + 32];
        float m = fmaxf(v0, v1);
#pragma unroll
        for (int off = 16; off > 0; off >>= 1)
            m = fmaxf(m, __shfl_xor_sync(0xffffffffu, m, off));
        float s = expf(v0 - m) + expf(v1 - m);
#pragma unroll
        for (int off = 16; off > 0; off >>= 1)
            s += __shfl_xor_sync(0xffffffffu, s, off);
        float ls = logf(s);
        out[base + lane] = v0 - m - ls;
        out[base + lane + 32] = v1 - m - ls;
        out[NCsz + base + lane] = v0;
        out[NCsz + base + lane + 32] = v1;
        atomicAdd(&colacc[lane], expf(v0));
        atomicAdd(&colacc[lane + 32], expf(v1));
    }
    __syncthreads();
    if (tid < CC) atomicAdd(&g_colsum[tid], colacc[tid]);
}

__global__ void k_colout(float* __restrict__ out, int N) {
    size_t NCsz = (size_t)N * CC;
    for (size_t idx = blockIdx.x * blockDim.x + threadIdx.x; idx < NCsz;
         idx += (size_t)gridDim.x * blockDim.x) {
        int c = (int)(idx & 63);
        out[2 * NCsz + idx] = expf(g_z[idx]) / g_colsum[c];
    }
}

// ---------------- launch ----------------
extern "C" void kernel_launch(void* const* d_in, const int* in_sizes, int n_in,
                              void* d_out, int out_size) {
    const float* x = (const float*)d_in[0];
    const int* ei = (const int*)d_in[1];
    const float* W1 = (const float*)d_in[2];
    const float* b1 = (const float*)d_in[3];
    const float* W2 = (const float*)d_in[4];
    const float* b2 = (const float*)d_in[5];
    float* out = (float*)d_out;

    int N = in_sizes[0] / FF;
    int E = in_sizes[1] / 2;
    int NB = cdiv(N, 512);

    // graph preprocessing (5 launches)
    k_zero_deg<<<cdiv(N, 256), 256>>>(N);
    k_count<<<cdiv(E, 256), 256>>>(ei, E);
    k_chunksum<<<NB, 512>>>(N);
    k_scan2<<<NB, 512>>>(N, NB);
    k_scatter<<<cdiv(E, 256), 256>>>(ei, E);

    // MLP (launch index 5 = k_gemm1 -> ncu -s 5 profiles it)
    k_gemm1<<<cdiv(N, 128), 512>>>(x, W1, b1, N);
    k_gemm2<<<cdiv(N, 128), 256>>>(W2, b2, N);

    // 10 hops (fp32 state; y0 produced by gemm2 epilogue into g_yA)
    // hops 0..8 ping-pong (hop 8 writes g_yB); last hop reads g_yB, emits z.
    int hop_blocks = cdiv(N, 8);
    for (int hop = 0; hop < K_HOPS - 1; hop++)
        k_hopf<<<hop_blocks, 256>>>(hop, N);
    k_hoplast<<<hop_blocks, 256>>>(N);

    // outputs
    k_rowsm<<<592, 256>>>(out, N);
    k_colout<<<cdiv(N * CC, 256), 256>>>(out, N);
}